// round 3
// baseline (speedup 1.0000x reference)
#include <cuda_runtime.h>

// Problem constants (fixed by the dataset): S=8192, N=2048, D=128, C=256
constexpr int D_ = 128;
constexpr int C_ = 256;
constexpr int QB = 16;     // queries per block in main kernel

// Scratch (no allocations allowed)
__device__ __align__(16) float  g_mus[C_ * D_];        // class sums [c][d]
__device__ float4               g_mus4[(D_ / 4) * C_]; // transposed [d4][c] as float4
__device__ float                g_s2[C_];              // ||mus_c||^2
__device__ float                g_cnt[C_];             // class counts (float)
__device__ float                g_loss;                // sum of -logp

// ---------------------------------------------------------------- zero
__global__ void k_zero() {
    int i = blockIdx.x * blockDim.x + threadIdx.x;
    if (i < C_ * D_) g_mus[i] = 0.0f;
    if (i < C_)      g_cnt[i] = 0.0f;
    if (i == 0)      g_loss   = 0.0f;
}

// ---------------------------------------------------------------- scatter class sums
// 2 support rows per 256-thread block; 128 threads per row (one per dim).
// NOTE: labels are int32 (JAX without x64 downcasts the reference's int64).
__global__ void k_accum(const float* __restrict__ xs,
                        const int* __restrict__ ys) {
    int s = blockIdx.x * 2 + (threadIdx.x >> 7);
    int d = threadIdx.x & 127;
    int c = ys[s] & (C_ - 1);              // mask keeps scatter in-bounds
    atomicAdd(&g_mus[c * D_ + d], xs[(size_t)s * D_ + d]);
    if (d == 0) atomicAdd(&g_cnt[c], 1.0f);
}

// ---------------------------------------------------------------- stats + transpose
// One block per class, 128 threads (one per dim).
__global__ void k_stats() {
    int c = blockIdx.x;
    int d = threadIdx.x;
    float v = g_mus[c * D_ + d];
    if ((d & 3) == 0) {
        float4 val = *reinterpret_cast<const float4*>(&g_mus[c * D_ + d]);
        g_mus4[(d >> 2) * C_ + c] = val;
    }
    float p = v * v;
    #pragma unroll
    for (int o = 16; o; o >>= 1) p += __shfl_down_sync(0xffffffffu, p, o);
    __shared__ float sp[4];
    if ((d & 31) == 0) sp[d >> 5] = p;
    __syncthreads();
    if (d == 0) g_s2[c] = sp[0] + sp[1] + sp[2] + sp[3];
}

// ---------------------------------------------------------------- main: logits + log-softmax + loss
__global__ void __launch_bounds__(256) k_main(const float* __restrict__ xq,
                                              const int* __restrict__ yq) {
    __shared__ float4 xq_s[QB * D_ / 4];   // 8 KB
    __shared__ float  logit_s[QB * C_];    // 16 KB
    __shared__ float  q2_s[QB];
    __shared__ int    y_s[QB];
    __shared__ float  warp_loss[8];

    const int t  = threadIdx.x;            // t == class index c
    const int q0 = blockIdx.x * QB;

    if (t < QB) { q2_s[t] = 0.0f; y_s[t] = yq[q0 + t] & (C_ - 1); }
    __syncthreads();

    // Load the 16x128 query tile (float4) and accumulate ||xq||^2 per query.
    const float4* src = reinterpret_cast<const float4*>(xq + (size_t)q0 * D_);
    #pragma unroll
    for (int i = t; i < QB * D_ / 4; i += 256) {
        float4 v = src[i];
        xq_s[i] = v;
        int q = (i * 4) / D_;              // 4 floats never straddle a query row
        atomicAdd(&q2_s[q], v.x * v.x + v.y * v.y + v.z * v.z + v.w * v.w);
    }

    // Hoist per-class scalars so their LDGs overlap the FFMA mainloop.
    const int   c   = t;
    const float s2  = g_s2[c];
    const float cnt = g_cnt[c];
    __syncthreads();

    // Dot products: thread c accumulates dot(xq_q, mus_c) for 16 queries.
    float acc[QB];
    #pragma unroll
    for (int q = 0; q < QB; q++) acc[q] = 0.0f;

    #pragma unroll 4
    for (int d4 = 0; d4 < D_ / 4; d4++) {
        float4 m = g_mus4[d4 * C_ + c];    // coalesced LDG.128 across threads
        #pragma unroll
        for (int q = 0; q < QB; q++) {
            float4 x = xq_s[q * (D_ / 4) + d4];  // smem broadcast
            acc[q] = fmaf(m.x, x.x, acc[q]);
            acc[q] = fmaf(m.y, x.y, acc[q]);
            acc[q] = fmaf(m.z, x.z, acc[q]);
            acc[q] = fmaf(m.w, x.w, acc[q]);
        }
    }

    #pragma unroll
    for (int q = 0; q < QB; q++) {
        float q2  = q2_s[q];
        float dot = acc[q];
        float del = (y_s[q] == c) ? 1.0f : 0.0f;
        float xqM = dot - del * q2;
        float M2  = s2 - del * (2.0f * dot - q2);
        float cn  = cnt - del;
        float den = fmaxf(cn, 0.1f);
        float inv = 1.0f / den;
        float l   = -0.5f * (q2 - 2.0f * xqM * inv + M2 * inv * inv);
        logit_s[q * C_ + c] = (cn > 0.1f) ? l : 0.0f;
    }
    __syncthreads();

    // Log-softmax over 256 classes: warp w handles queries 2w and 2w+1.
    const int w = t >> 5, lane = t & 31;
    float wl = 0.0f;
    #pragma unroll
    for (int k = 0; k < 2; k++) {
        int q = 2 * w + k;
        float vals[8];
        float vmax = -1e30f;
        #pragma unroll
        for (int i = 0; i < 8; i++) {
            vals[i] = logit_s[q * C_ + lane + 32 * i];
            vmax = fmaxf(vmax, vals[i]);
        }
        #pragma unroll
        for (int o = 16; o; o >>= 1) vmax = fmaxf(vmax, __shfl_xor_sync(0xffffffffu, vmax, o));
        float se = 0.0f;
        #pragma unroll
        for (int i = 0; i < 8; i++) se += __expf(vals[i] - vmax);
        #pragma unroll
        for (int o = 16; o; o >>= 1) se += __shfl_xor_sync(0xffffffffu, se, o);
        if (lane == 0) {
            float ly = logit_s[q * C_ + y_s[q]];
            wl += (vmax + __logf(se)) - ly;    // -log p(target)
        }
    }
    if (lane == 0) warp_loss[w] = wl;
    __syncthreads();
    if (t == 0) {
        float s = 0.0f;
        #pragma unroll
        for (int i = 0; i < 8; i++) s += warp_loss[i];
        atomicAdd(&g_loss, s);
    }
}

// ---------------------------------------------------------------- finalize
__global__ void k_final(float* __restrict__ out, int N) {
    out[0] = g_loss / (float)N;
}

// ---------------------------------------------------------------- launcher
extern "C" void kernel_launch(void* const* d_in, const int* in_sizes, int n_in,
                              void* d_out, int out_size) {
    const float* xq = (const float*)d_in[0];
    const int*   yq = (const int*)d_in[1];
    const float* xs = (const float*)d_in[2];
    const int*   ys = (const int*)d_in[3];
    // d_in[4] = pos (unused: yq == ys[pos] already)

    const int N = in_sizes[1];   // 2048
    const int S = in_sizes[3];   // 8192

    k_zero<<<(C_ * D_ + 255) / 256, 256>>>();
    k_accum<<<S / 2, 256>>>(xs, ys);
    k_stats<<<C_, 128>>>();
    k_main<<<N / QB, 256>>>(xq, yq);
    k_final<<<1, 1>>>((float*)d_out, N);
}

// round 4
// speedup vs baseline: 1.2720x; 1.2720x over previous
#include <cuda_runtime.h>

// Problem constants (fixed by the dataset): S=8192, N=2048, D=128, C=256
constexpr int D_ = 128;
constexpr int C_ = 256;
constexpr int QB = 8;      // queries per block in main kernel

// Scratch (no allocations allowed)
__device__ __align__(16) float  g_mus[C_ * D_];        // class sums [c][d]
__device__ __align__(16) float4 g_mus4[(D_ / 4) * C_]; // transposed [d4][c] as float4
__device__ float                g_s2[C_];              // ||mus_c||^2
__device__ float                g_cnt[C_];             // class counts (float)
__device__ float                g_loss;                // sum of -logp

// Packed dual-lane FP32 FMA (sm_103a): d = a*b + c on two f32 lanes per issue.
__device__ __forceinline__ unsigned long long ffma2(unsigned long long a,
                                                    unsigned long long b,
                                                    unsigned long long c) {
    unsigned long long d;
    asm("fma.rn.f32x2 %0, %1, %2, %3;" : "=l"(d) : "l"(a), "l"(b), "l"(c));
    return d;
}
__device__ __forceinline__ float f32x2_sum(unsigned long long v) {
    float lo, hi;
    asm("mov.b64 {%0, %1}, %2;" : "=f"(lo), "=f"(hi) : "l"(v));
    return lo + hi;
}

// ---------------------------------------------------------------- zero
__global__ void k_zero() {
    int i = blockIdx.x * blockDim.x + threadIdx.x;
    if (i < C_ * D_) g_mus[i] = 0.0f;
    if (i < C_)      g_cnt[i] = 0.0f;
    if (i == 0)      g_loss   = 0.0f;
}

// ---------------------------------------------------------------- scatter class sums
// 2 support rows per 256-thread block; 128 threads per row (one per dim).
// NOTE: labels are int32 (JAX without x64 downcasts the reference's int64).
__global__ void k_accum(const float* __restrict__ xs,
                        const int* __restrict__ ys) {
    int s = blockIdx.x * 2 + (threadIdx.x >> 7);
    int d = threadIdx.x & 127;
    int c = ys[s] & (C_ - 1);              // mask keeps scatter in-bounds
    atomicAdd(&g_mus[c * D_ + d], xs[(size_t)s * D_ + d]);
    if (d == 0) atomicAdd(&g_cnt[c], 1.0f);
}

// ---------------------------------------------------------------- stats + transpose
// One block per class, 128 threads (one per dim).
__global__ void k_stats() {
    int c = blockIdx.x;
    int d = threadIdx.x;
    float v = g_mus[c * D_ + d];
    if ((d & 3) == 0) {
        float4 val = *reinterpret_cast<const float4*>(&g_mus[c * D_ + d]);
        g_mus4[(d >> 2) * C_ + c] = val;
    }
    float p = v * v;
    #pragma unroll
    for (int o = 16; o; o >>= 1) p += __shfl_down_sync(0xffffffffu, p, o);
    __shared__ float sp[4];
    if ((d & 31) == 0) sp[d >> 5] = p;
    __syncthreads();
    if (d == 0) g_s2[c] = sp[0] + sp[1] + sp[2] + sp[3];
}

// ---------------------------------------------------------------- main
// 512 threads: thread = (h, c), h = dim-half (0/1), c = class.
// Each thread: 8 queries x 64 dims of dot product via FFMA2, then the two
// halves combine through smem, h=0 does the per-(q,c) logit epilogue, and
// warps 0..7 do the 256-wide log-softmax (one query per warp).
__global__ void __launch_bounds__(512) k_main(const float* __restrict__ xq,
                                              const int* __restrict__ yq) {
    __shared__ float4 xq_s[QB * D_ / 4];   // 4 KB
    __shared__ float  part_s[QB * C_];     // 8 KB: h=1 partial dots
    __shared__ float  logit_s[QB * C_];    // 8 KB
    __shared__ float  q2_s[QB];
    __shared__ int    y_s[QB];
    __shared__ float  warp_loss[QB];

    const int t  = threadIdx.x;
    const int c  = t & (C_ - 1);
    const int h  = t >> 8;                 // dim-half
    const int q0 = blockIdx.x * QB;

    if (t < QB) { q2_s[t] = 0.0f; y_s[t] = yq[q0 + t] & (C_ - 1); }
    __syncthreads();

    // Load the 8x128 query tile (float4) and accumulate ||xq||^2 per query.
    const float4* src = reinterpret_cast<const float4*>(xq + (size_t)q0 * D_);
    if (t < QB * D_ / 4) {
        float4 v = src[t];
        xq_s[t] = v;
        int q = (t * 4) / D_;
        atomicAdd(&q2_s[q], v.x * v.x + v.y * v.y + v.z * v.z + v.w * v.w);
    }

    // Per-class scalars (LDGs overlap the mainloop wind-up).
    const float s2  = g_s2[c];
    const float cnt = g_cnt[c];
    __syncthreads();

    // Dot products over this thread's 64-dim half, packed f32x2.
    const ulonglong2* mus2 = reinterpret_cast<const ulonglong2*>(g_mus4);
    const ulonglong2* xs2  = reinterpret_cast<const ulonglong2*>(xq_s);

    unsigned long long acc[QB];
    #pragma unroll
    for (int q = 0; q < QB; q++) acc[q] = 0ull;

    const int d4_0 = h * (D_ / 8);         // 16 float4 chunks per half
    #pragma unroll 4
    for (int i = 0; i < D_ / 8; i++) {
        int d4 = d4_0 + i;
        ulonglong2 m = mus2[d4 * C_ + c];  // coalesced LDG.128 across classes
        #pragma unroll
        for (int q = 0; q < QB; q++) {
            ulonglong2 x = xs2[q * (D_ / 4) + d4];  // smem broadcast
            acc[q] = ffma2(m.x, x.x, acc[q]);
            acc[q] = ffma2(m.y, x.y, acc[q]);
        }
    }

    float dotq[QB];
    #pragma unroll
    for (int q = 0; q < QB; q++) dotq[q] = f32x2_sum(acc[q]);

    if (h == 1) {
        #pragma unroll
        for (int q = 0; q < QB; q++) part_s[q * C_ + c] = dotq[q];
    }
    __syncthreads();

    if (h == 0) {
        #pragma unroll
        for (int q = 0; q < QB; q++) {
            float q2  = q2_s[q];
            float dot = dotq[q] + part_s[q * C_ + c];
            float del = (y_s[q] == c) ? 1.0f : 0.0f;
            float xqM = dot - del * q2;
            float M2  = s2 - del * (2.0f * dot - q2);
            float cn  = cnt - del;
            float den = fmaxf(cn, 0.1f);
            float inv = 1.0f / den;
            float l   = -0.5f * (q2 - 2.0f * xqM * inv + M2 * inv * inv);
            logit_s[q * C_ + c] = (cn > 0.1f) ? l : 0.0f;
        }
    }
    __syncthreads();

    // Log-softmax: warp w (w < 8) handles query w.
    const int w = t >> 5, lane = t & 31;
    if (w < QB) {
        float vals[C_ / 32];
        float vmax = -1e30f;
        #pragma unroll
        for (int i = 0; i < C_ / 32; i++) {
            vals[i] = logit_s[w * C_ + lane + 32 * i];
            vmax = fmaxf(vmax, vals[i]);
        }
        #pragma unroll
        for (int o = 16; o; o >>= 1) vmax = fmaxf(vmax, __shfl_xor_sync(0xffffffffu, vmax, o));
        float se = 0.0f;
        #pragma unroll
        for (int i = 0; i < C_ / 32; i++) se += __expf(vals[i] - vmax);
        #pragma unroll
        for (int o = 16; o; o >>= 1) se += __shfl_xor_sync(0xffffffffu, se, o);
        if (lane == 0) {
            float ly = logit_s[w * C_ + y_s[w]];
            warp_loss[w] = (vmax + __logf(se)) - ly;   // -log p(target)
        }
    }
    __syncthreads();
    if (t == 0) {
        float s = 0.0f;
        #pragma unroll
        for (int i = 0; i < QB; i++) s += warp_loss[i];
        atomicAdd(&g_loss, s);
    }
}

// ---------------------------------------------------------------- finalize
__global__ void k_final(float* __restrict__ out, int N) {
    out[0] = g_loss / (float)N;
}

// ---------------------------------------------------------------- launcher
extern "C" void kernel_launch(void* const* d_in, const int* in_sizes, int n_in,
                              void* d_out, int out_size) {
    const float* xq = (const float*)d_in[0];
    const int*   yq = (const int*)d_in[1];
    const float* xs = (const float*)d_in[2];
    const int*   ys = (const int*)d_in[3];
    // d_in[4] = pos (unused: yq == ys[pos] already)

    const int N = in_sizes[1];   // 2048
    const int S = in_sizes[3];   // 8192

    k_zero<<<(C_ * D_ + 255) / 256, 256>>>();
    k_accum<<<S / 2, 256>>>(xs, ys);
    k_stats<<<C_, 128>>>();
    k_main<<<N / QB, 512>>>(xq, yq);
    k_final<<<1, 1>>>((float*)d_out, N);
}